// round 12
// baseline (speedup 1.0000x reference)
#include <cuda_runtime.h>
#include <math.h>

#define S_SAMPLES 512
#define VDIM      128
#define NVOX      (VDIM * VDIM * VDIM)   // 2097152
#define NWORDS    (NVOX / 32)            // 65536 words per bitmap
#define DET       128
#define NPIX      (DET * DET)            // 16384

// Hybrid storage, natural (vx, vy, vz) indexing everywhere:
//  - FRONTAL volumes (view 0): BITMAPS. word = (vx*128+vy)*4 + vz/32, bit = vz&31.
//    bp lanes differ in vy -> distinct words; march along vz -> one register-
//    accumulated REDG.OR per ~12 samples.
//  - LATERAL volumes (view 1): BYTE volumes. bp lanes differ in vz -> fully
//    coalesced byte stores (proven best path).
// gt float index = 32*word + bit = voxel index (exact layout match).
// Invariant: all zero at entry to kernel_launch (static init + the reduce
// consumes-and-rezeroes everything it reads).
__device__ unsigned int g_bitsF[2][NWORDS];              // 512 KB
__device__ __align__(16) unsigned char g_volL[2][NVOX];  // 4 MB
__device__ double       g_acc = 0.0;
__device__ unsigned int g_ctr = 0;

// ---------------------------------------------------------------------------
// Backprojection: one thread per ray; clip sample range to the voxel box,
// march IN VOXEL SPACE (q(t) affine in t).
// ---------------------------------------------------------------------------
__global__ void __launch_bounds__(256)
bp_kernel(const float* __restrict__ predF,
          const float* __restrict__ predL,
          const float* __restrict__ srcF,
          const float* __restrict__ tgtF,
          const float* __restrict__ srcL,
          const float* __restrict__ tgtL,
          const float* __restrict__ Ainv,
          const float* __restrict__ tinv)
{
    int p = blockIdx.x * blockDim.x + threadIdx.x;
    int slice = blockIdx.y;          // 0..3
    int view  = slice & 1;           // 0 = frontal, 1 = lateral
    int batch = slice >> 1;

    const float* mask = (view ? predL : predF) + batch * NPIX;
    if (!(mask[p] > 0.5f)) return;   // inactive pixel: nothing to do

    const float* src = view ? srcL : srcF;
    const float* tgt = (view ? tgtL : tgtF) + 3 * p;

    float sx = src[0], sy = src[1], sz = src[2];
    float dx = tgt[0] - sx, dy = tgt[1] - sy, dz = tgt[2] - sz;
    float len = sqrtf(dx * dx + dy * dy + dz * dz);
    float inv = 1.0f / (len + 1e-8f);
    dx *= inv; dy *= inv; dz *= inv;
    float L = len * 2.5f;

    float a00 = Ainv[0], a01 = Ainv[1], a02 = Ainv[2];
    float a10 = Ainv[3], a11 = Ainv[4], a12 = Ainv[5];
    float a20 = Ainv[6], a21 = Ainv[7], a22 = Ainv[8];

    // Voxel-space ray: q(t) = q0 + t*qd   (affine in t)
    float q0x = a00 * sx + a01 * sy + a02 * sz + tinv[0];
    float q0y = a10 * sx + a11 * sy + a12 * sz + tinv[1];
    float q0z = a20 * sx + a21 * sy + a22 * sz + tinv[2];
    float qdx = a00 * dx + a01 * dy + a02 * dz;
    float qdy = a10 * dx + a11 * dy + a12 * dz;
    float qdz = a20 * dx + a21 * dy + a22 * dz;

    const float LOQ = -0.501f;                  // round() valid window with margin
    const float HIQ = (float)VDIM - 0.499f;
    float tlo = 0.0f, thi = L;
    {
        float q0a[3] = {q0x, q0y, q0z};
        float qda[3] = {qdx, qdy, qdz};
        #pragma unroll
        for (int ax = 0; ax < 3; ax++) {
            float q0 = q0a[ax], qd = qda[ax];
            if (fabsf(qd) < 1e-9f) {
                if (q0 < LOQ || q0 > HIQ) { tlo = 1.0f; thi = 0.0f; }
            } else {
                float u1 = (LOQ - q0) / qd;
                float u2 = (HIQ - q0) / qd;
                tlo = fmaxf(tlo, fminf(u1, u2));
                thi = fminf(thi, fmaxf(u1, u2));
            }
        }
    }
    if (thi < tlo) return;

    float dt = L * (1.0f / (S_SAMPLES - 1));
    int klo = max(0,             (int)floorf(tlo / dt) - 2);   // safety margin:
    int khi = min(S_SAMPLES - 1, (int)ceilf (thi / dt) + 2);   // per-sample check authoritative

    // Pre-scale direction by L: q = fma(tv, rd, q0), tv = k/(S-1)
    float rdx = L * qdx, rdy = L * qdy, rdz = L * qdz;
    const float c1 = 1.0f / (S_SAMPLES - 1);

    if (view == 0) {
        // ---- frontal: bitmap with register-accumulated REDG.OR flush -------
        unsigned int* bits = g_bitsF[batch];
        int prevw = -1;
        unsigned int acc = 0u;
        for (int k = klo; k <= khi; k++) {
            float tv = (float)k * c1;                      // jnp.linspace(0,1,S)
            int vx = __float2int_rn(fmaf(tv, rdx, q0x));   // ties-to-even = jnp.round
            int vy = __float2int_rn(fmaf(tv, rdy, q0y));
            int vz = __float2int_rn(fmaf(tv, rdz, q0z));
            if ((unsigned)vx < (unsigned)VDIM &&
                (unsigned)vy < (unsigned)VDIM &&
                (unsigned)vz < (unsigned)VDIM) {
                int word = (((vx << 7) + vy) << 2) + (vz >> 5);
                unsigned int b = 1u << (vz & 31);
                if (word == prevw) {
                    acc |= b;                              // same word: local OR
                } else {
                    if (prevw >= 0) atomicOr(&bits[prevw], acc);   // REDG.OR
                    prevw = word;
                    acc = b;
                }
            }
        }
        if (prevw >= 0) atomicOr(&bits[prevw], acc);
    } else {
        // ---- lateral: byte volume, coalesced idempotent stores -------------
        unsigned char* vol = g_volL[batch];
        for (int k = klo; k <= khi; k++) {
            float tv = (float)k * c1;
            int vx = __float2int_rn(fmaf(tv, rdx, q0x));
            int vy = __float2int_rn(fmaf(tv, rdy, q0y));
            int vz = __float2int_rn(fmaf(tv, rdz, q0z));
            if ((unsigned)vx < (unsigned)VDIM &&
                (unsigned)vy < (unsigned)VDIM &&
                (unsigned)vz < (unsigned)VDIM) {
                vol[(vx * VDIM + vy) * VDIM + vz] = 1;   // lanes contiguous in vz
            }
        }
    }
}

// ---------------------------------------------------------------------------
// BCE + finalize + re-zero, fused. Grid (128, 4) x 256 threads; one thread
// per 16 vz voxels: vy = vy0 + t/8, half-word hw = t&7 (vz = 16*hw..+15).
// NO smem, NO transpose, NO barrier — frontal bits are vz-ordered like gt.
//
// Exact decomposition (sF, sL binary):
//   b[sF+sL] + g*(sF+sL) = B0 + (sF+sL)*(CC + g) + KAPPA*(sF & sL)
// B0*(2*NVOX) folded into the finalizer; intersections counted via popc.
// Frontal nibble -> byte-mask expansion: (nib * 0x00204081) & 0x01010101.
// Every word/byte read is immediately re-zeroed for the next call.
// ---------------------------------------------------------------------------
#define CC_F    (-0.62011450695827750f)   // b1 - b0
#define KAPPA_F (-0.19355181656647243f)   // b2 - 2*b1 + b0
#define B0_D    (-0.69314718055994531)    // log(0.5)

__device__ __forceinline__ float warp_sum(float v) {
    #pragma unroll
    for (int o = 16; o > 0; o >>= 1) v += __shfl_down_sync(0xffffffffu, v, o);
    return v;
}

__global__ void __launch_bounds__(256)
reduce_kernel(const float* __restrict__ gt, float* __restrict__ out)
{
    __shared__ float sh[8];
    int t  = threadIdx.x;
    int vx = blockIdx.x;
    int vy = blockIdx.y * 32 + (t >> 3);
    int hw = t & 7;                       // 16-voxel half-word along vz
    int row  = (vx << 7) + vy;            // (vx*128 + vy)
    int w32  = (row << 2) + (hw >> 1);    // frontal word index
    int sub  = hw & 1;
    int lbase = (row << 5) + (hw << 2);   // lateral/gt word index (4 words = 16 vox)

    // ---- issue ALL loads up front (MLP 14) --------------------------------
    unsigned int F0 = g_bitsF[0][w32];
    unsigned int F1 = g_bitsF[1][w32];
    unsigned int l0[4], l1[4];
    float4 gv[4];
    #pragma unroll
    for (int q = 0; q < 4; q++) {
        l0[q] = reinterpret_cast<const unsigned int*>(g_volL[0])[lbase + q];
        l1[q] = reinterpret_cast<const unsigned int*>(g_volL[1])[lbase + q];
        gv[q] = reinterpret_cast<const float4*>(gt)[lbase + q];
    }

    // ---- consume-and-reset ------------------------------------------------
    // sub==0 lane zeroes the shared frontal word; its pair lane (same warp)
    // already issued the load above (single LDG instruction precedes the STG
    // in the warp's instruction stream), so no race.
    if (sub == 0) {
        g_bitsF[0][w32] = 0u;
        g_bitsF[1][w32] = 0u;
    }
    #pragma unroll
    for (int q = 0; q < 4; q++) {
        reinterpret_cast<unsigned int*>(g_volL[0])[lbase + q] = 0u;
        reinterpret_cast<unsigned int*>(g_volL[1])[lbase + q] = 0u;
    }

    // ---- this thread's 16-bit frontal halves ------------------------------
    int shft = sub << 4;
    unsigned int f0h = (F0 >> shft) & 0xffffu;
    unsigned int f1h = (F1 >> shft) & 0xffffu;

    // ---- compute (pure register math) -------------------------------------
    float sum  = 0.0f;
    int   icnt = 0;
    #pragma unroll
    for (int q = 0; q < 4; q++) {
        unsigned int fw0 = (((f0h >> (4 * q)) & 0xFu) * 0x00204081u) & 0x01010101u;
        unsigned int fw1 = (((f1h >> (4 * q)) & 0xFu) * 0x00204081u) & 0x01010101u;
        icnt += __popc(l0[q] & fw0) + __popc(l1[q] & fw1);     // intersections
        unsigned int s0 = l0[q] + fw0;       // bytewise sums (each <= 2, no carry)
        unsigned int s1 = l1[q] + fw1;
        float cgx = CC_F + gv[q].x;
        float cgy = CC_F + gv[q].y;
        float cgz = CC_F + gv[q].z;
        float cgw = CC_F + gv[q].w;
        sum = fmaf((float)( s0        & 255u), cgx, sum);
        sum = fmaf((float)((s0 >>  8) & 255u), cgy, sum);
        sum = fmaf((float)((s0 >> 16) & 255u), cgz, sum);
        sum = fmaf((float)( s0 >> 24        ), cgw, sum);
        sum = fmaf((float)( s1        & 255u), cgx, sum);
        sum = fmaf((float)((s1 >>  8) & 255u), cgy, sum);
        sum = fmaf((float)((s1 >> 16) & 255u), cgz, sum);
        sum = fmaf((float)( s1 >> 24        ), cgw, sum);
    }
    sum = fmaf(KAPPA_F, (float)icnt, sum);

    // ---- block reduce -> global atomic -> last-block finalize -------------
    sum = warp_sum(sum);
    int lane = t & 31, w = t >> 5;
    if (lane == 0) sh[w] = sum;
    __syncthreads();
    if (w == 0) {
        float v = (lane < 8) ? sh[lane] : 0.0f;
        v = warp_sum(v);
        if (lane == 0) {
            atomicAdd(&g_acc, (double)v);
            __threadfence();
            unsigned int total = gridDim.x * gridDim.y;
            unsigned int done = atomicInc(&g_ctr, total - 1);   // self-resetting
            if (done == total - 1) {
                double acc = atomicAdd(&g_acc, 0.0);            // atomic read
                // loss = -( 2*NVOX*B0 + acc ) / (2*NVOX) = -B0 - acc/(2*NVOX)
                out[0] = (float)(-B0_D - acc / (2.0 * (double)NVOX));
                g_acc = 0.0;                                    // reset for next call
            }
        }
    }
}

// ---------------------------------------------------------------------------
extern "C" void kernel_launch(void* const* d_in, const int* in_sizes, int n_in,
                              void* d_out, int out_size)
{
    const float* predF = (const float*)d_in[0];
    const float* predL = (const float*)d_in[1];
    const float* srcF  = (const float*)d_in[2];
    const float* tgtF  = (const float*)d_in[3];
    const float* srcL  = (const float*)d_in[4];
    const float* tgtL  = (const float*)d_in[5];
    const float* gt    = (const float*)d_in[6];
    const float* Ainv  = (const float*)d_in[7];
    const float* tinv  = (const float*)d_in[8];
    float* out = (float*)d_out;

    dim3 bp_grid(NPIX / 256, 4);              // 64 x 4 = 256 blocks
    bp_kernel<<<bp_grid, 256>>>(predF, predL, srcF, tgtF, srcL, tgtL, Ainv, tinv);

    dim3 rd_grid(VDIM, 4);                    // 512 blocks x 256 threads
    reduce_kernel<<<rd_grid, 256>>>(gt, out);
}

// round 13
// speedup vs baseline: 1.0368x; 1.0368x over previous
#include <cuda_runtime.h>
#include <math.h>

#define S_SAMPLES 512
#define VDIM      128
#define NVOX      (VDIM * VDIM * VDIM)   // 2097152
#define NWORDS    (NVOX / 32)            // 65536 words per bitmap
#define DET       128
#define NPIX      (DET * DET)            // 16384

// Hybrid storage, natural (vx, vy, vz) indexing everywhere:
//  - FRONTAL volumes (view 0): BITMAPS. word = (vx*128+vy)*4 + vz/32, bit = vz&31.
//    bp lanes differ in vy -> distinct words; march along vz -> one register-
//    accumulated REDG.OR per ~12 samples.
//  - LATERAL volumes (view 1): BYTE volumes. bp lanes differ in vz -> fully
//    coalesced byte stores (proven best path).
// gt float index = voxel index (exact layout match).
// Invariant: all zero at entry to kernel_launch (static init + the reduce
// consumes-and-rezeroes everything it reads).
__device__ unsigned int g_bitsF[2][NWORDS];              // 512 KB
__device__ __align__(16) unsigned char g_volL[2][NVOX];  // 4 MB
__device__ double       g_acc = 0.0;
__device__ unsigned int g_ctr = 0;

// ---------------------------------------------------------------------------
// Backprojection (R12 body, unchanged): one thread per ray; clip to box,
// march in voxel space.
// ---------------------------------------------------------------------------
__global__ void __launch_bounds__(256)
bp_kernel(const float* __restrict__ predF,
          const float* __restrict__ predL,
          const float* __restrict__ srcF,
          const float* __restrict__ tgtF,
          const float* __restrict__ srcL,
          const float* __restrict__ tgtL,
          const float* __restrict__ Ainv,
          const float* __restrict__ tinv)
{
    int p = blockIdx.x * blockDim.x + threadIdx.x;
    int slice = blockIdx.y;          // 0..3
    int view  = slice & 1;           // 0 = frontal, 1 = lateral
    int batch = slice >> 1;

    const float* mask = (view ? predL : predF) + batch * NPIX;
    if (!(mask[p] > 0.5f)) return;   // inactive pixel: nothing to do

    const float* src = view ? srcL : srcF;
    const float* tgt = (view ? tgtL : tgtF) + 3 * p;

    float sx = src[0], sy = src[1], sz = src[2];
    float dx = tgt[0] - sx, dy = tgt[1] - sy, dz = tgt[2] - sz;
    float len = sqrtf(dx * dx + dy * dy + dz * dz);
    float inv = 1.0f / (len + 1e-8f);
    dx *= inv; dy *= inv; dz *= inv;
    float L = len * 2.5f;

    float a00 = Ainv[0], a01 = Ainv[1], a02 = Ainv[2];
    float a10 = Ainv[3], a11 = Ainv[4], a12 = Ainv[5];
    float a20 = Ainv[6], a21 = Ainv[7], a22 = Ainv[8];

    // Voxel-space ray: q(t) = q0 + t*qd   (affine in t)
    float q0x = a00 * sx + a01 * sy + a02 * sz + tinv[0];
    float q0y = a10 * sx + a11 * sy + a12 * sz + tinv[1];
    float q0z = a20 * sx + a21 * sy + a22 * sz + tinv[2];
    float qdx = a00 * dx + a01 * dy + a02 * dz;
    float qdy = a10 * dx + a11 * dy + a12 * dz;
    float qdz = a20 * dx + a21 * dy + a22 * dz;

    const float LOQ = -0.501f;                  // round() valid window with margin
    const float HIQ = (float)VDIM - 0.499f;
    float tlo = 0.0f, thi = L;
    {
        float q0a[3] = {q0x, q0y, q0z};
        float qda[3] = {qdx, qdy, qdz};
        #pragma unroll
        for (int ax = 0; ax < 3; ax++) {
            float q0 = q0a[ax], qd = qda[ax];
            if (fabsf(qd) < 1e-9f) {
                if (q0 < LOQ || q0 > HIQ) { tlo = 1.0f; thi = 0.0f; }
            } else {
                float u1 = (LOQ - q0) / qd;
                float u2 = (HIQ - q0) / qd;
                tlo = fmaxf(tlo, fminf(u1, u2));
                thi = fminf(thi, fmaxf(u1, u2));
            }
        }
    }
    if (thi < tlo) return;

    float dt = L * (1.0f / (S_SAMPLES - 1));
    int klo = max(0,             (int)floorf(tlo / dt) - 2);   // safety margin:
    int khi = min(S_SAMPLES - 1, (int)ceilf (thi / dt) + 2);   // per-sample check authoritative

    float rdx = L * qdx, rdy = L * qdy, rdz = L * qdz;
    const float c1 = 1.0f / (S_SAMPLES - 1);

    if (view == 0) {
        // ---- frontal: bitmap with register-accumulated REDG.OR flush -------
        unsigned int* bits = g_bitsF[batch];
        int prevw = -1;
        unsigned int acc = 0u;
        for (int k = klo; k <= khi; k++) {
            float tv = (float)k * c1;                      // jnp.linspace(0,1,S)
            int vx = __float2int_rn(fmaf(tv, rdx, q0x));   // ties-to-even = jnp.round
            int vy = __float2int_rn(fmaf(tv, rdy, q0y));
            int vz = __float2int_rn(fmaf(tv, rdz, q0z));
            if ((unsigned)vx < (unsigned)VDIM &&
                (unsigned)vy < (unsigned)VDIM &&
                (unsigned)vz < (unsigned)VDIM) {
                int word = (((vx << 7) + vy) << 2) + (vz >> 5);
                unsigned int b = 1u << (vz & 31);
                if (word == prevw) {
                    acc |= b;                              // same word: local OR
                } else {
                    if (prevw >= 0) atomicOr(&bits[prevw], acc);   // REDG.OR
                    prevw = word;
                    acc = b;
                }
            }
        }
        if (prevw >= 0) atomicOr(&bits[prevw], acc);
    } else {
        // ---- lateral: byte volume, coalesced idempotent stores -------------
        unsigned char* vol = g_volL[batch];
        for (int k = klo; k <= khi; k++) {
            float tv = (float)k * c1;
            int vx = __float2int_rn(fmaf(tv, rdx, q0x));
            int vy = __float2int_rn(fmaf(tv, rdy, q0y));
            int vz = __float2int_rn(fmaf(tv, rdz, q0z));
            if ((unsigned)vx < (unsigned)VDIM &&
                (unsigned)vy < (unsigned)VDIM &&
                (unsigned)vz < (unsigned)VDIM) {
                vol[(vx * VDIM + vy) * VDIM + vz] = 1;   // lanes contiguous in vz
            }
        }
    }
}

// ---------------------------------------------------------------------------
// BCE + finalize + re-zero, fused. Grid (128, 8) x 256 threads = 1024 blocks
// (~55 warps/SM; the 512-block R12 shape was grid-limited at ~27). One thread
// per 8 vz voxels: vy = vy0 + t/16, octet o = t&15 (vz = 8o..8o+7).
// NO smem transpose, NO barrier — frontal bits are vz-ordered like gt.
//
// Exact decomposition (sF, sL binary):
//   b[sF+sL] + g*(sF+sL) = B0 + (sF+sL)*(CC + g) + KAPPA*(sF & sL)
// B0*(2*NVOX) folded into the finalizer; intersections counted via popc.
// Frontal nibble -> byte-mask expansion: (nib * 0x00204081) & 0x01010101.
// Every word/byte read is immediately re-zeroed for the next call.
// ---------------------------------------------------------------------------
#define CC_F    (-0.62011450695827750f)   // b1 - b0
#define KAPPA_F (-0.19355181656647243f)   // b2 - 2*b1 + b0
#define B0_D    (-0.69314718055994531)    // log(0.5)

__device__ __forceinline__ float warp_sum(float v) {
    #pragma unroll
    for (int o = 16; o > 0; o >>= 1) v += __shfl_down_sync(0xffffffffu, v, o);
    return v;
}

__global__ void __launch_bounds__(256)
reduce_kernel(const float* __restrict__ gt, float* __restrict__ out)
{
    __shared__ float sh[8];
    int t  = threadIdx.x;
    int vx = blockIdx.x;
    int vy = blockIdx.y * 16 + (t >> 4);
    int o  = t & 15;                      // vz octet: vz = 8o .. 8o+7
    int row   = (vx << 7) + vy;           // vx*128 + vy
    int w32   = (row << 2) + (o >> 2);    // frontal word index
    int bsel  = o & 3;                    // byte within frontal word
    int lbase = (row << 5) + (o << 1);    // lateral/gt 4B-word index (2 words)

    // ---- issue ALL loads up front (MLP 8) ---------------------------------
    unsigned int F0 = g_bitsF[0][w32];
    unsigned int F1 = g_bitsF[1][w32];
    unsigned int l0[2], l1[2];
    float4 gv[2];
    #pragma unroll
    for (int q = 0; q < 2; q++) {
        l0[q] = reinterpret_cast<const unsigned int*>(g_volL[0])[lbase + q];
        l1[q] = reinterpret_cast<const unsigned int*>(g_volL[1])[lbase + q];
        gv[q] = reinterpret_cast<const float4*>(gt)[lbase + q];
    }

    // ---- consume-and-reset ------------------------------------------------
    // Each frontal word is shared by 4 consecutive threads of ONE warp (same
    // vy row => same warp). All their LDGs issue before this STG instruction
    // in the warp's in-order stream, so load-before-zero holds.
    if (bsel == 0) {
        g_bitsF[0][w32] = 0u;
        g_bitsF[1][w32] = 0u;
    }
    #pragma unroll
    for (int q = 0; q < 2; q++) {
        reinterpret_cast<unsigned int*>(g_volL[0])[lbase + q] = 0u;
        reinterpret_cast<unsigned int*>(g_volL[1])[lbase + q] = 0u;
    }

    // ---- this thread's 8-bit frontal slices -------------------------------
    int shft = bsel << 3;
    unsigned int f0b = (F0 >> shft) & 0xffu;
    unsigned int f1b = (F1 >> shft) & 0xffu;

    // ---- compute (pure register math) -------------------------------------
    float sum  = 0.0f;
    int   icnt = 0;
    #pragma unroll
    for (int q = 0; q < 2; q++) {
        unsigned int fw0 = (((f0b >> (4 * q)) & 0xFu) * 0x00204081u) & 0x01010101u;
        unsigned int fw1 = (((f1b >> (4 * q)) & 0xFu) * 0x00204081u) & 0x01010101u;
        icnt += __popc(l0[q] & fw0) + __popc(l1[q] & fw1);     // intersections
        unsigned int s0 = l0[q] + fw0;       // bytewise sums (each <= 2, no carry)
        unsigned int s1 = l1[q] + fw1;
        float cgx = CC_F + gv[q].x;
        float cgy = CC_F + gv[q].y;
        float cgz = CC_F + gv[q].z;
        float cgw = CC_F + gv[q].w;
        sum = fmaf((float)( s0        & 255u), cgx, sum);
        sum = fmaf((float)((s0 >>  8) & 255u), cgy, sum);
        sum = fmaf((float)((s0 >> 16) & 255u), cgz, sum);
        sum = fmaf((float)( s0 >> 24        ), cgw, sum);
        sum = fmaf((float)( s1        & 255u), cgx, sum);
        sum = fmaf((float)((s1 >>  8) & 255u), cgy, sum);
        sum = fmaf((float)((s1 >> 16) & 255u), cgz, sum);
        sum = fmaf((float)( s1 >> 24        ), cgw, sum);
    }
    sum = fmaf(KAPPA_F, (float)icnt, sum);

    // ---- block reduce -> global atomic -> last-block finalize -------------
    sum = warp_sum(sum);
    int lane = t & 31, w = t >> 5;
    if (lane == 0) sh[w] = sum;
    __syncthreads();
    if (w == 0) {
        float v = (lane < 8) ? sh[lane] : 0.0f;
        v = warp_sum(v);
        if (lane == 0) {
            atomicAdd(&g_acc, (double)v);
            __threadfence();
            unsigned int total = gridDim.x * gridDim.y;
            unsigned int done = atomicInc(&g_ctr, total - 1);   // self-resetting
            if (done == total - 1) {
                double acc = atomicAdd(&g_acc, 0.0);            // atomic read
                // loss = -( 2*NVOX*B0 + acc ) / (2*NVOX) = -B0 - acc/(2*NVOX)
                out[0] = (float)(-B0_D - acc / (2.0 * (double)NVOX));
                g_acc = 0.0;                                    // reset for next call
            }
        }
    }
}

// ---------------------------------------------------------------------------
extern "C" void kernel_launch(void* const* d_in, const int* in_sizes, int n_in,
                              void* d_out, int out_size)
{
    const float* predF = (const float*)d_in[0];
    const float* predL = (const float*)d_in[1];
    const float* srcF  = (const float*)d_in[2];
    const float* tgtF  = (const float*)d_in[3];
    const float* srcL  = (const float*)d_in[4];
    const float* tgtL  = (const float*)d_in[5];
    const float* gt    = (const float*)d_in[6];
    const float* Ainv  = (const float*)d_in[7];
    const float* tinv  = (const float*)d_in[8];
    float* out = (float*)d_out;

    dim3 bp_grid(NPIX / 256, 4);              // 64 x 4 = 256 blocks
    bp_kernel<<<bp_grid, 256>>>(predF, predL, srcF, tgtF, srcL, tgtL, Ainv, tinv);

    dim3 rd_grid(VDIM, 8);                    // 1024 blocks x 256 threads
    reduce_kernel<<<rd_grid, 256>>>(gt, out);
}